// round 11
// baseline (speedup 1.0000x reference)
#include <cuda_runtime.h>
#include <math.h>

#define N_NODES 50000
#define N_EDGES 800000
#define F 64
#define BIN_CAP 64

// ---------------- scratch (device globals: no allocation allowed) ----------
__device__ float g_deg [N_NODES];
__device__ float g_dinv[N_NODES];
__device__ int   g_cnt [N_NODES];
__device__ int2  g_bin [N_NODES * BIN_CAP];   // {src, edge-weight-as-bits} per dst
__device__ float g_tx1 [N_NODES * F];         // L_hat @ x
__device__ float g_tx2 [N_NODES * F];         // L_hat @ tx1 (raw; Tx2 = 2*this - x)

// ---------------------------------------------------------------------------
__global__ void zero_kernel() {
    int i = blockIdx.x * blockDim.x + threadIdx.x;
    if (i < N_NODES) { g_deg[i] = 0.f; g_cnt[i] = 0; }
}

// fused: degree accumulation (on src) + dst-binning of {src, ew}; 2 edges/thread
__global__ void deg_place_kernel(const int* __restrict__ ei, const float* __restrict__ ew) {
    int t = blockIdx.x * blockDim.x + threadIdx.x;
    if (t >= N_EDGES / 2) return;
    int2   s2 = reinterpret_cast<const int2*>(ei)[t];
    int2   d2 = reinterpret_cast<const int2*>(ei + N_EDGES)[t];
    float2 w2 = reinterpret_cast<const float2*>(ew)[t];
    atomicAdd(&g_deg[s2.x], w2.x);
    atomicAdd(&g_deg[s2.y], w2.y);
    int r0 = atomicAdd(&g_cnt[d2.x], 1);
    if (r0 < BIN_CAP)
        g_bin[(size_t)d2.x * BIN_CAP + r0] = make_int2(s2.x, __float_as_int(w2.x));
    int r1 = atomicAdd(&g_cnt[d2.y], 1);
    if (r1 < BIN_CAP)
        g_bin[(size_t)d2.y * BIN_CAP + r1] = make_int2(s2.y, __float_as_int(w2.y));
}

__global__ void dinv_kernel() {
    int i = blockIdx.x * blockDim.x + threadIdx.x;
    if (i < N_NODES) {
        float d = g_deg[i];
        g_dinv[i] = (d > 0.f) ? rsqrtf(d) : 0.f;
    }
}

// ---------------------------------------------------------------------------
// Gather-propagate, one warp per node, QUAD-edge steps.
//   w = -dinv[src] * ew * dinv[dst]
// 8 lanes per edge (ql = lane&7 -> 8-float row segment, 2x float4/lane),
// 4 edges per step (quarter = lane>>3).  steps = ceil(rem/4): a deg-16 node
// finishes in ONE unrolled batch with 8 independent LDG.128 per lane in
// flight.  Padding (<=3 dummy edges) hits {s=0,w=0} -> row 0, L1-resident.
// Combine across quarters via 2 shfl_down rounds; lanes 0-7 write the row.
// ---------------------------------------------------------------------------
__global__ void prop_gather(const float* __restrict__ sfeat,
                            float* __restrict__ dfeat) {
    int node = (blockIdx.x * blockDim.x + threadIdx.x) >> 5;
    if (node >= N_NODES) return;
    const int lane    = threadIdx.x & 31;
    const int quarter = lane >> 3;       // which edge in the group of 4
    const int ql      = lane & 7;        // 8-float segment within the row

    int cnt = g_cnt[node];
    if (cnt > BIN_CAP) cnt = BIN_CAP;
    const float ddst = g_dinv[node];
    const int2* bin = g_bin + (size_t)node * BIN_CAP;

    float4 a0 = make_float4(0.f, 0.f, 0.f, 0.f);
    float4 a1 = make_float4(0.f, 0.f, 0.f, 0.f);

    for (int base = 0; base < cnt; base += 32) {
        int rem = cnt - base;
        if (rem > 32) rem = 32;
        int2 p = make_int2(0, 0);
        float w_own = 0.f;
        if (lane < rem) {
            p = bin[base + lane];
            w_own = -g_dinv[p.x] * __int_as_float(p.y) * ddst;
        }
        int steps = (rem + 3) >> 2;
#pragma unroll 4
        for (int j = 0; j < steps; j++) {
            int idx = 4 * j + quarter;   // may hit a zeroed lane (padding)
            int   s = __shfl_sync(0xffffffffu, p.x, idx);
            float w = __shfl_sync(0xffffffffu, w_own, idx);
            const float* row = sfeat + (size_t)s * F + ql * 8;
            float4 v0 = *reinterpret_cast<const float4*>(row);
            float4 v1 = *reinterpret_cast<const float4*>(row + 4);
            a0.x = fmaf(w, v0.x, a0.x);
            a0.y = fmaf(w, v0.y, a0.y);
            a0.z = fmaf(w, v0.z, a0.z);
            a0.w = fmaf(w, v0.w, a0.w);
            a1.x = fmaf(w, v1.x, a1.x);
            a1.y = fmaf(w, v1.y, a1.y);
            a1.z = fmaf(w, v1.z, a1.z);
            a1.w = fmaf(w, v1.w, a1.w);
        }
    }

    // combine quarters: lane l += lane l+16, then lane l += lane l+8
#pragma unroll
    for (int o = 16; o >= 8; o >>= 1) {
        a0.x += __shfl_down_sync(0xffffffffu, a0.x, o);
        a0.y += __shfl_down_sync(0xffffffffu, a0.y, o);
        a0.z += __shfl_down_sync(0xffffffffu, a0.z, o);
        a0.w += __shfl_down_sync(0xffffffffu, a0.w, o);
        a1.x += __shfl_down_sync(0xffffffffu, a1.x, o);
        a1.y += __shfl_down_sync(0xffffffffu, a1.y, o);
        a1.z += __shfl_down_sync(0xffffffffu, a1.z, o);
        a1.w += __shfl_down_sync(0xffffffffu, a1.w, o);
    }
    if (quarter == 0) {
        float* drow = dfeat + (size_t)node * F + ql * 8;
        *reinterpret_cast<float4*>(drow)     = a0;
        *reinterpret_cast<float4*>(drow + 4) = a1;
    }
}

// ---------------------------------------------------------------------------
// Fused gate GEMM (tf32 tensor cores) + GRU epilogue + output projection.
//  t[n] = [x_n | Tx1_n | (2*Tx2raw_n - x_n)]  (192)
//  z  = sigmoid(t@Wz + b), ht = tanh(t@Wh + b)
//  out[n] = sigmoid( sum_c (1-z_c)*ht_c * wlin_c + blin )
// (R6 gate body: single As buffer, two syncs per k-chunk.)
// ---------------------------------------------------------------------------
#define WSTR 132
#define ASTR 36
#define GATE_SMEM ((192 * WSTR + 128 * ASTR + 3 * 64) * 4)

__device__ __forceinline__ float tf32r(float x) {
    unsigned u;
    asm("cvt.rna.tf32.f32 %0, %1;" : "=r"(u) : "f"(x));
    return __uint_as_float(u);
}

__device__ __forceinline__ void mma_tf32(float& c0, float& c1, float& c2, float& c3,
                                         float a0, float a1, float a2, float a3,
                                         float b0, float b1) {
    asm volatile(
        "mma.sync.aligned.m16n8k8.row.col.f32.tf32.tf32.f32 "
        "{%0,%1,%2,%3}, {%4,%5,%6,%7}, {%8,%9}, {%0,%1,%2,%3};\n"
        : "+f"(c0), "+f"(c1), "+f"(c2), "+f"(c3)
        : "r"(__float_as_uint(a0)), "r"(__float_as_uint(a1)),
          "r"(__float_as_uint(a2)), "r"(__float_as_uint(a3)),
          "r"(__float_as_uint(b0)), "r"(__float_as_uint(b1)));
}

__device__ __forceinline__ float sigm(float v) { return 1.f / (1.f + __expf(-v)); }

__global__ void gate_mma_kernel(const float* __restrict__ x,
                                const float* __restrict__ Wxz,
                                const float* __restrict__ bxz,
                                const float* __restrict__ bhz,
                                const float* __restrict__ Wxh,
                                const float* __restrict__ bxh,
                                const float* __restrict__ bhh,
                                const float* __restrict__ wlin,
                                const float* __restrict__ blin,
                                float* __restrict__ out) {
    extern __shared__ float sm[];
    float* Ws = sm;                    // 192*132 tf32-rounded weights (permuted)
    float* As = Ws + 192 * WSTR;       // 128*36 tf32-rounded activations
    float* bz = As + 128 * ASTR;       // 64
    float* bh = bz + 64;               // 64
    float* wl = bh + 64;               // 64

    const int tid  = threadIdx.x;
    const int lane = tid & 31;
    const int wid  = tid >> 5;
    const int g    = lane >> 2;
    const int tig  = lane & 3;
    const int wm   = wid & 3;
    const int wn   = wid >> 2;
    const int block0 = blockIdx.x * 128;

    for (int m = tid; m < 192 * 128; m += 256) {
        int k = m >> 7, c = m & 127;
        int kb = k >> 6, kr = k & 63;
        float v = (c < 64) ? Wxz[kb * 4096 + kr * 64 + c]
                           : Wxh[kb * 4096 + kr * 64 + (c - 64)];
        int cp = (c & 7) * 16 + (c >> 6) * 8 + ((c >> 3) & 7);
        Ws[k * WSTR + cp] = tf32r(v);
    }
    if (tid < 64) {
        bz[tid] = bxz[tid] + bhz[tid];
        bh[tid] = bxh[tid] + bhh[tid];
        wl[tid] = wlin[tid];
    }

    float acc[2][8][4];
#pragma unroll
    for (int mt = 0; mt < 2; mt++)
#pragma unroll
        for (int nt = 0; nt < 8; nt++)
#pragma unroll
            for (int j = 0; j < 4; j++) { acc[mt][nt][j] = 0.f; }

    const int row_ld = tid >> 1;
    const int kq = (tid & 1) * 16;
    const int node_ld = block0 + row_ld;
    const bool okn = node_ld < N_NODES;
    const size_t off = (size_t)node_ld * F;

    for (int ck = 0; ck < 6; ck++) {
        float4 q[4];
        if (okn) {
            int kg = ck * 32 + kq;
            if (ck < 2) {
                const float* p = x + off + kg;
#pragma unroll
                for (int i = 0; i < 4; i++) q[i] = *reinterpret_cast<const float4*>(p + 4 * i);
            } else if (ck < 4) {
                const float* p = g_tx1 + off + (kg - 64);
#pragma unroll
                for (int i = 0; i < 4; i++) q[i] = *reinterpret_cast<const float4*>(p + 4 * i);
            } else {
                const float* p  = g_tx2 + off + (kg - 128);
                const float* px = x + off + (kg - 128);
#pragma unroll
                for (int i = 0; i < 4; i++) {
                    float4 a = *reinterpret_cast<const float4*>(p + 4 * i);
                    float4 b = *reinterpret_cast<const float4*>(px + 4 * i);
                    q[i] = make_float4(2.f * a.x - b.x, 2.f * a.y - b.y,
                                       2.f * a.z - b.z, 2.f * a.w - b.w);
                }
            }
        } else {
#pragma unroll
            for (int i = 0; i < 4; i++) q[i] = make_float4(0.f, 0.f, 0.f, 0.f);
        }
#pragma unroll
        for (int i = 0; i < 4; i++) {
            q[i].x = tf32r(q[i].x); q[i].y = tf32r(q[i].y);
            q[i].z = tf32r(q[i].z); q[i].w = tf32r(q[i].w);
        }

        __syncthreads();
#pragma unroll
        for (int i = 0; i < 4; i++)
            *reinterpret_cast<float4*>(As + row_ld * ASTR + kq + 4 * i) = q[i];
        __syncthreads();

#pragma unroll
        for (int ks = 0; ks < 4; ks++) {
            const float* ab = As + ks * 8 + tig;
            float a[2][4];
#pragma unroll
            for (int mt = 0; mt < 2; mt++) {
                int r0 = wm * 32 + mt * 16 + g;
                a[mt][0] = ab[r0 * ASTR];
                a[mt][1] = ab[(r0 + 8) * ASTR];
                a[mt][2] = ab[r0 * ASTR + 4];
                a[mt][3] = ab[(r0 + 8) * ASTR + 4];
            }
            const float* wb = Ws + (ck * 32 + ks * 8 + tig) * WSTR + g * 16 + wn * 8;
            float4 p0 = *reinterpret_cast<const float4*>(wb);
            float4 p1 = *reinterpret_cast<const float4*>(wb + 4);
            float4 p2 = *reinterpret_cast<const float4*>(wb + 4 * WSTR);
            float4 p3 = *reinterpret_cast<const float4*>(wb + 4 * WSTR + 4);
            float b0a[8] = {p0.x, p0.y, p0.z, p0.w, p1.x, p1.y, p1.z, p1.w};
            float b1a[8] = {p2.x, p2.y, p2.z, p2.w, p3.x, p3.y, p3.z, p3.w};
#pragma unroll
            for (int nt = 0; nt < 8; nt++)
#pragma unroll
                for (int mt = 0; mt < 2; mt++)
                    mma_tf32(acc[mt][nt][0], acc[mt][nt][1],
                             acc[mt][nt][2], acc[mt][nt][3],
                             a[mt][0], a[mt][1], a[mt][2], a[mt][3],
                             b0a[nt], b1a[nt]);
        }
    }

    __syncthreads();
    float* bufA = sm;               // 128 x 65  (1 - z)
    float* bufB = sm + 128 * 65;    // 128 x 65  (ht * wlin)

#pragma unroll
    for (int mt = 0; mt < 2; mt++) {
        int r0 = wm * 32 + mt * 16 + g;
        int r1 = r0 + 8;
#pragma unroll
        for (int nt = 0; nt < 8; nt++) {
            int c = nt * 8 + 2 * tig;
            if (wn == 0) {
                bufA[r0 * 65 + c]     = 1.f - sigm(acc[mt][nt][0] + bz[c]);
                bufA[r0 * 65 + c + 1] = 1.f - sigm(acc[mt][nt][1] + bz[c + 1]);
                bufA[r1 * 65 + c]     = 1.f - sigm(acc[mt][nt][2] + bz[c]);
                bufA[r1 * 65 + c + 1] = 1.f - sigm(acc[mt][nt][3] + bz[c + 1]);
            } else {
                bufB[r0 * 65 + c]     = tanhf(acc[mt][nt][0] + bh[c]) * wl[c];
                bufB[r0 * 65 + c + 1] = tanhf(acc[mt][nt][1] + bh[c + 1]) * wl[c + 1];
                bufB[r1 * 65 + c]     = tanhf(acc[mt][nt][2] + bh[c]) * wl[c];
                bufB[r1 * 65 + c + 1] = tanhf(acc[mt][nt][3] + bh[c + 1]) * wl[c + 1];
            }
        }
    }
    __syncthreads();

    if (tid < 128) {
        int ng = block0 + tid;
        if (ng < N_NODES) {
            float s = 0.f;
#pragma unroll 8
            for (int c = 0; c < 64; c++)
                s += bufA[tid * 65 + c] * bufB[tid * 65 + c];
            out[ng] = sigm(s + blin[0]);
        }
    }
}

// ---------------------------------------------------------------------------
extern "C" void kernel_launch(void* const* d_in, const int* in_sizes, int n_in,
                              void* d_out, int out_size) {
    const float* x    = (const float*)d_in[0];
    const int*   ei   = (const int*)  d_in[1];
    const float* ew   = (const float*)d_in[2];
    const float* Wxz  = (const float*)d_in[3];
    const float* bxz  = (const float*)d_in[4];
    const float* bhz  = (const float*)d_in[6];
    // d_in[5]=W_hz, [7..10]=W_xr/b_xr/W_hr/b_hr: dead (H=0 makes R unused)
    const float* Wxh  = (const float*)d_in[11];
    const float* bxh  = (const float*)d_in[12];
    const float* bhh  = (const float*)d_in[14];
    const float* wlin = (const float*)d_in[15];
    const float* blin = (const float*)d_in[16];
    float* out = (float*)d_out;

    const int TB = 256;
    zero_kernel     <<<(N_NODES + TB - 1) / TB, TB>>>();
    deg_place_kernel<<<(N_EDGES / 2 + TB - 1) / TB, TB>>>(ei, ew);
    dinv_kernel     <<<(N_NODES + TB - 1) / TB, TB>>>();

    const int PTB = 128;   // smaller blocks: finer load balance for Poisson degrees
    const int PROP_BLOCKS = (N_NODES * 32 + PTB - 1) / PTB;
    float* tx1p; cudaGetSymbolAddress((void**)&tx1p, g_tx1);
    float* tx2p; cudaGetSymbolAddress((void**)&tx2p, g_tx2);
    prop_gather<<<PROP_BLOCKS, PTB>>>(x, tx1p);
    prop_gather<<<PROP_BLOCKS, PTB>>>(tx1p, tx2p);

    cudaFuncSetAttribute(gate_mma_kernel,
                         cudaFuncAttributeMaxDynamicSharedMemorySize, GATE_SMEM);
    gate_mma_kernel<<<(N_NODES + 127) / 128, 256, GATE_SMEM>>>(
        x, Wxz, bxz, bhz, Wxh, bxh, bhh, wlin, blin, out);
}

// round 12
// speedup vs baseline: 1.2943x; 1.2943x over previous
#include <cuda_runtime.h>
#include <math.h>

#define N_NODES 50000
#define N_EDGES 800000
#define F 64
#define BIN_CAP 64

// ---------------- scratch (device globals: no allocation allowed) ----------
__device__ float g_deg [N_NODES];
__device__ float g_dinv[N_NODES];
__device__ int   g_cnt [N_NODES];
__device__ int2  g_bin [N_NODES * BIN_CAP];   // {src, edge-weight-as-bits} per dst
__device__ float g_tx1 [N_NODES * F];         // L_hat @ x
__device__ float g_tx2 [N_NODES * F];         // L_hat @ tx1 (raw; Tx2 = 2*this - x)

// ---------------------------------------------------------------------------
__global__ void zero_kernel() {
    int i = blockIdx.x * blockDim.x + threadIdx.x;
    if (i < N_NODES) { g_deg[i] = 0.f; g_cnt[i] = 0; }
}

// fused: degree accumulation (on src) + dst-binning of {src, ew}; 2 edges/thread
__global__ void deg_place_kernel(const int* __restrict__ ei, const float* __restrict__ ew) {
    int t = blockIdx.x * blockDim.x + threadIdx.x;
    if (t >= N_EDGES / 2) return;
    int2   s2 = reinterpret_cast<const int2*>(ei)[t];
    int2   d2 = reinterpret_cast<const int2*>(ei + N_EDGES)[t];
    float2 w2 = reinterpret_cast<const float2*>(ew)[t];
    atomicAdd(&g_deg[s2.x], w2.x);
    atomicAdd(&g_deg[s2.y], w2.y);
    int r0 = atomicAdd(&g_cnt[d2.x], 1);
    if (r0 < BIN_CAP)
        g_bin[(size_t)d2.x * BIN_CAP + r0] = make_int2(s2.x, __float_as_int(w2.x));
    int r1 = atomicAdd(&g_cnt[d2.y], 1);
    if (r1 < BIN_CAP)
        g_bin[(size_t)d2.y * BIN_CAP + r1] = make_int2(s2.y, __float_as_int(w2.y));
}

__global__ void dinv_kernel() {
    int i = blockIdx.x * blockDim.x + threadIdx.x;
    if (i < N_NODES) {
        float d = g_deg[i];
        g_dinv[i] = (d > 0.f) ? rsqrtf(d) : 0.f;
    }
}

// ---------------------------------------------------------------------------
// Gather-propagate, one warp per node (R10 body — DO NOT TOUCH; local opt).
//   w = -dinv[src] * ew * dinv[dst]
// 16 lanes per edge (float4/lane), 2 edges per step, dynamic trip count.
// ---------------------------------------------------------------------------
__global__ void prop_gather(const float* __restrict__ sfeat,
                            float* __restrict__ dfeat) {
    int node = (blockIdx.x * blockDim.x + threadIdx.x) >> 5;
    if (node >= N_NODES) return;
    const int lane = threadIdx.x & 31;
    const int half = lane >> 4;          // 0: even edge, 1: odd edge
    const int fl   = lane & 15;          // float4 slot within the 64-float row

    int cnt = g_cnt[node];
    if (cnt > BIN_CAP) cnt = BIN_CAP;
    const float ddst = g_dinv[node];
    const int2* bin = g_bin + (size_t)node * BIN_CAP;

    float4 acc = make_float4(0.f, 0.f, 0.f, 0.f);

    for (int base = 0; base < cnt; base += 32) {
        int rem = cnt - base;
        if (rem > 32) rem = 32;
        int2 p = make_int2(0, 0);
        float w_own = 0.f;
        if (lane < rem) {
            p = bin[base + lane];
            w_own = -g_dinv[p.x] * __int_as_float(p.y) * ddst;
        }
        int steps = (rem + 1) >> 1;
#pragma unroll 4
        for (int j = 0; j < steps; j++) {
            int idx = 2 * j + half;      // may hit a zeroed lane when rem is odd
            int   s = __shfl_sync(0xffffffffu, p.x, idx);
            float w = __shfl_sync(0xffffffffu, w_own, idx);
            float4 v = *reinterpret_cast<const float4*>(
                sfeat + (size_t)s * F + fl * 4);
            acc.x = fmaf(w, v.x, acc.x);
            acc.y = fmaf(w, v.y, acc.y);
            acc.z = fmaf(w, v.z, acc.z);
            acc.w = fmaf(w, v.w, acc.w);
        }
    }

    acc.x += __shfl_down_sync(0xffffffffu, acc.x, 16);
    acc.y += __shfl_down_sync(0xffffffffu, acc.y, 16);
    acc.z += __shfl_down_sync(0xffffffffu, acc.z, 16);
    acc.w += __shfl_down_sync(0xffffffffu, acc.w, 16);
    if (half == 0)
        *reinterpret_cast<float4*>(dfeat + (size_t)node * F + fl * 4) = acc;
}

// ---------------------------------------------------------------------------
// Fused gate GEMM (tf32 tensor cores) + GRU epilogue + output projection.
//  t[n] = [x_n | Tx1_n | (2*Tx2raw_n - x_n)]  (192)
//  z  = sigmoid(t@Wz + b), ht = tanh(t@Wh + b)
//  out[n] = sigmoid( sum_c (1-z_c)*ht_c * wlin_c + blin )
// WEIGHTS STREAMED PER 32-ROW K-CHUNK (17KB slice) instead of 99KB upfront:
// prefetched to regs alongside the activation loads, stored behind the SAME
// two syncs the As tile needs.  Smem drops to 67KB (sized by the epilogue
// buffers) -> 2 CTAs/SM: waves 3 -> 2, cross-CTA latency hiding.
// ---------------------------------------------------------------------------
#define WSTR 132
#define ASTR 36
#define GATE_SMEM ((128 * 65 * 2 + 3 * 64) * 4)   // 67,328 B (epilogue-sized)

__device__ __forceinline__ float tf32r(float x) {
    unsigned u;
    asm("cvt.rna.tf32.f32 %0, %1;" : "=r"(u) : "f"(x));
    return __uint_as_float(u);
}

__device__ __forceinline__ void mma_tf32(float& c0, float& c1, float& c2, float& c3,
                                         float a0, float a1, float a2, float a3,
                                         float b0, float b1) {
    asm volatile(
        "mma.sync.aligned.m16n8k8.row.col.f32.tf32.tf32.f32 "
        "{%0,%1,%2,%3}, {%4,%5,%6,%7}, {%8,%9}, {%0,%1,%2,%3};\n"
        : "+f"(c0), "+f"(c1), "+f"(c2), "+f"(c3)
        : "r"(__float_as_uint(a0)), "r"(__float_as_uint(a1)),
          "r"(__float_as_uint(a2)), "r"(__float_as_uint(a3)),
          "r"(__float_as_uint(b0)), "r"(__float_as_uint(b1)));
}

__device__ __forceinline__ float sigm(float v) { return 1.f / (1.f + __expf(-v)); }

__global__ void __launch_bounds__(256, 2)
gate_mma_kernel(const float* __restrict__ x,
                const float* __restrict__ Wxz,
                const float* __restrict__ bxz,
                const float* __restrict__ bhz,
                const float* __restrict__ Wxh,
                const float* __restrict__ bxh,
                const float* __restrict__ bhh,
                const float* __restrict__ wlin,
                const float* __restrict__ blin,
                float* __restrict__ out) {
    extern __shared__ float sm[];
    float* Wc = sm;                     // 32*132 streamed weight slice (tf32, permuted)
    float* As = Wc + 32 * WSTR;         // 128*36 tf32 activations
    float* bz = sm + 128 * 65 * 2;      // bias past the epilogue buffers
    float* bh = bz + 64;
    float* wl = bh + 64;

    const int tid  = threadIdx.x;
    const int lane = tid & 31;
    const int wid  = tid >> 5;
    const int g    = lane >> 2;
    const int tig  = lane & 3;
    const int wm   = wid & 3;
    const int wn   = wid >> 2;
    const int block0 = blockIdx.x * 128;

    if (tid < 64) {
        bz[tid] = bxz[tid] + bhz[tid];
        bh[tid] = bxh[tid] + bhh[tid];
        wl[tid] = wlin[tid];
    }

    // --- per-thread weight staging geometry (constant across chunks) ---
    // this thread stages column c = tid&127, local rows kr = t7 + 2i (i<16)
    const int c  = tid & 127;
    const int t7 = tid >> 7;                              // 0 or 1
    const int cp = (c & 7) * 16 + (c >> 6) * 8 + ((c >> 3) & 7);
    const float* wsrc = (c < 64) ? (Wxz + c) : (Wxh + (c - 64));
    float* wdst = Wc + t7 * WSTR + cp;                    // + i*(2*WSTR)

    float acc[2][8][4];
#pragma unroll
    for (int mt = 0; mt < 2; mt++)
#pragma unroll
        for (int nt = 0; nt < 8; nt++)
#pragma unroll
            for (int j = 0; j < 4; j++) { acc[mt][nt][j] = 0.f; }

    const int row_ld = tid >> 1;
    const int kq = (tid & 1) * 16;
    const int node_ld = block0 + row_ld;
    const bool okn = node_ld < N_NODES;
    const size_t off = (size_t)node_ld * F;

    for (int ck = 0; ck < 6; ck++) {
        // ---- prefetch this chunk's weight slice (16 vals, imm offsets) ----
        // global k = ck*32 + kr; kb = ck>>1, krow = (ck&1)*32 + kr
        const float* wp = wsrc + (ck >> 1) * 4096 + (ck & 1) * 2048 + t7 * 64;
        float wv[16];
#pragma unroll
        for (int i = 0; i < 16; i++) wv[i] = wp[i * 128];

        // ---- activation fetch ----
        float4 q[4];
        if (okn) {
            int kg = ck * 32 + kq;
            if (ck < 2) {
                const float* p = x + off + kg;
#pragma unroll
                for (int i = 0; i < 4; i++) q[i] = *reinterpret_cast<const float4*>(p + 4 * i);
            } else if (ck < 4) {
                const float* p = g_tx1 + off + (kg - 64);
#pragma unroll
                for (int i = 0; i < 4; i++) q[i] = *reinterpret_cast<const float4*>(p + 4 * i);
            } else {
                const float* p  = g_tx2 + off + (kg - 128);
                const float* px = x + off + (kg - 128);
#pragma unroll
                for (int i = 0; i < 4; i++) {
                    float4 a = *reinterpret_cast<const float4*>(p + 4 * i);
                    float4 b = *reinterpret_cast<const float4*>(px + 4 * i);
                    q[i] = make_float4(2.f * a.x - b.x, 2.f * a.y - b.y,
                                       2.f * a.z - b.z, 2.f * a.w - b.w);
                }
            }
        } else {
#pragma unroll
            for (int i = 0; i < 4; i++) q[i] = make_float4(0.f, 0.f, 0.f, 0.f);
        }
#pragma unroll
        for (int i = 0; i < 4; i++) {
            q[i].x = tf32r(q[i].x); q[i].y = tf32r(q[i].y);
            q[i].z = tf32r(q[i].z); q[i].w = tf32r(q[i].w);
        }

        __syncthreads();   // previous chunk's As/Wc reads complete
#pragma unroll
        for (int i = 0; i < 4; i++)
            *reinterpret_cast<float4*>(As + row_ld * ASTR + kq + 4 * i) = q[i];
#pragma unroll
        for (int i = 0; i < 16; i++)
            wdst[i * (2 * WSTR)] = tf32r(wv[i]);
        __syncthreads();   // As + Wc (and on ck=0: bias) visible

#pragma unroll
        for (int ks = 0; ks < 4; ks++) {
            const float* ab = As + ks * 8 + tig;
            float a[2][4];
#pragma unroll
            for (int mt = 0; mt < 2; mt++) {
                int r0 = wm * 32 + mt * 16 + g;
                a[mt][0] = ab[r0 * ASTR];
                a[mt][1] = ab[(r0 + 8) * ASTR];
                a[mt][2] = ab[r0 * ASTR + 4];
                a[mt][3] = ab[(r0 + 8) * ASTR + 4];
            }
            const float* wb = Wc + (ks * 8 + tig) * WSTR + g * 16 + wn * 8;
            float4 p0 = *reinterpret_cast<const float4*>(wb);
            float4 p1 = *reinterpret_cast<const float4*>(wb + 4);
            float4 p2 = *reinterpret_cast<const float4*>(wb + 4 * WSTR);
            float4 p3 = *reinterpret_cast<const float4*>(wb + 4 * WSTR + 4);
            float b0a[8] = {p0.x, p0.y, p0.z, p0.w, p1.x, p1.y, p1.z, p1.w};
            float b1a[8] = {p2.x, p2.y, p2.z, p2.w, p3.x, p3.y, p3.z, p3.w};
#pragma unroll
            for (int nt = 0; nt < 8; nt++)
#pragma unroll
                for (int mt = 0; mt < 2; mt++)
                    mma_tf32(acc[mt][nt][0], acc[mt][nt][1],
                             acc[mt][nt][2], acc[mt][nt][3],
                             a[mt][0], a[mt][1], a[mt][2], a[mt][3],
                             b0a[nt], b1a[nt]);
        }
    }

    __syncthreads();
    float* bufA = sm;               // 128 x 65  (1 - z)
    float* bufB = sm + 128 * 65;    // 128 x 65  (ht * wlin)

#pragma unroll
    for (int mt = 0; mt < 2; mt++) {
        int r0 = wm * 32 + mt * 16 + g;
        int r1 = r0 + 8;
#pragma unroll
        for (int nt = 0; nt < 8; nt++) {
            int cc = nt * 8 + 2 * tig;
            if (wn == 0) {
                bufA[r0 * 65 + cc]     = 1.f - sigm(acc[mt][nt][0] + bz[cc]);
                bufA[r0 * 65 + cc + 1] = 1.f - sigm(acc[mt][nt][1] + bz[cc + 1]);
                bufA[r1 * 65 + cc]     = 1.f - sigm(acc[mt][nt][2] + bz[cc]);
                bufA[r1 * 65 + cc + 1] = 1.f - sigm(acc[mt][nt][3] + bz[cc + 1]);
            } else {
                bufB[r0 * 65 + cc]     = tanhf(acc[mt][nt][0] + bh[cc]) * wl[cc];
                bufB[r0 * 65 + cc + 1] = tanhf(acc[mt][nt][1] + bh[cc + 1]) * wl[cc + 1];
                bufB[r1 * 65 + cc]     = tanhf(acc[mt][nt][2] + bh[cc]) * wl[cc];
                bufB[r1 * 65 + cc + 1] = tanhf(acc[mt][nt][3] + bh[cc + 1]) * wl[cc + 1];
            }
        }
    }
    __syncthreads();

    if (tid < 128) {
        int ng = block0 + tid;
        if (ng < N_NODES) {
            float s = 0.f;
#pragma unroll 8
            for (int cc = 0; cc < 64; cc++)
                s += bufA[tid * 65 + cc] * bufB[tid * 65 + cc];
            out[ng] = sigm(s + blin[0]);
        }
    }
}

// ---------------------------------------------------------------------------
extern "C" void kernel_launch(void* const* d_in, const int* in_sizes, int n_in,
                              void* d_out, int out_size) {
    const float* x    = (const float*)d_in[0];
    const int*   ei   = (const int*)  d_in[1];
    const float* ew   = (const float*)d_in[2];
    const float* Wxz  = (const float*)d_in[3];
    const float* bxz  = (const float*)d_in[4];
    const float* bhz  = (const float*)d_in[6];
    // d_in[5]=W_hz, [7..10]=W_xr/b_xr/W_hr/b_hr: dead (H=0 makes R unused)
    const float* Wxh  = (const float*)d_in[11];
    const float* bxh  = (const float*)d_in[12];
    const float* bhh  = (const float*)d_in[14];
    const float* wlin = (const float*)d_in[15];
    const float* blin = (const float*)d_in[16];
    float* out = (float*)d_out;

    const int TB = 256;
    zero_kernel     <<<(N_NODES + TB - 1) / TB, TB>>>();
    deg_place_kernel<<<(N_EDGES / 2 + TB - 1) / TB, TB>>>(ei, ew);
    dinv_kernel     <<<(N_NODES + TB - 1) / TB, TB>>>();

    const int PTB = 128;   // smaller blocks: finer load balance for Poisson degrees
    const int PROP_BLOCKS = (N_NODES * 32 + PTB - 1) / PTB;
    float* tx1p; cudaGetSymbolAddress((void**)&tx1p, g_tx1);
    float* tx2p; cudaGetSymbolAddress((void**)&tx2p, g_tx2);
    prop_gather<<<PROP_BLOCKS, PTB>>>(x, tx1p);
    prop_gather<<<PROP_BLOCKS, PTB>>>(tx1p, tx2p);

    cudaFuncSetAttribute(gate_mma_kernel,
                         cudaFuncAttributeMaxDynamicSharedMemorySize, GATE_SMEM);
    gate_mma_kernel<<<(N_NODES + 127) / 128, 256, GATE_SMEM>>>(
        x, Wxz, bxz, bhz, Wxh, bxh, bhh, wlin, blin, out);
}